// round 11
// baseline (speedup 1.0000x reference)
#include <cuda_runtime.h>
#include <math.h>

#define DZ 64
#define HY 112
#define WX 112
#define SLICE (HY*WX)        /* 12544 */
#define NN (DZ*SLICE)        /* 802816 */
#define NNU 802816u
#define NN4 (NN/4)           /* 200704 */
#define BM_WORDS (1u<<23)    /* bitmap for key values in [0, 2^28): 32MB */
#define MAXSRC 512           /* valid src labels are <= 334 */
#define WRAP_LO ((unsigned int)(0x100000000ull - NNU))  /* base >= this can wrap */

__device__ int                d_parent[NN];
__device__ int                d_labels[NN];
__device__ unsigned char      d_cat[NN];
__device__ int                d_fg[MAXSRC];
__device__ int                d_bg[MAXSRC];
__device__ unsigned long long d_lsum[NN];
__device__ int                d_ccnt[NN];
__device__ unsigned int       d_bitmap[BM_WORDS];
__device__ unsigned long long d_gsum;
__device__ int                d_gregs;

// 13 lexicographically-negative offsets {dz,dy,dx,is6}
__device__ __constant__ int c_off[13][4] = {
    {-1,-1,-1,0},{-1,-1, 0,0},{-1,-1, 1,0},
    {-1, 0,-1,0},{-1, 0, 0,1},{-1, 0, 1,0},
    {-1, 1,-1,0},{-1, 1, 0,0},{-1, 1, 1,0},
    { 0,-1,-1,0},{ 0,-1, 0,1},{ 0,-1, 1,0},
    { 0, 0,-1,1}
};

// ---------------------------------------------------------------- clear (uint4)
__global__ void k_clear() {
    unsigned int idx = blockIdx.x * blockDim.x + threadIdx.x;
    unsigned int stride = gridDim.x * blockDim.x;
    uint4 z4 = make_uint4(0u, 0u, 0u, 0u);
    uint4* bm = (uint4*)d_bitmap;                   // 2M uint4
    for (unsigned int i = idx; i < (BM_WORDS >> 2); i += stride) bm[i] = z4;
    uint4* ls = (uint4*)d_lsum;                     // NN/2 uint4
    for (unsigned int i = idx; i < (NN >> 1); i += stride) ls[i] = z4;
    uint4* cc = (uint4*)d_ccnt;                     // NN/4 uint4
    for (unsigned int i = idx; i < (NN >> 2); i += stride) cc[i] = z4;
    if (idx < MAXSRC) { d_fg[idx] = 0; d_bg[idx] = 0; }
    if (idx == 0) { d_gsum = 0ull; d_gregs = 0; }
}

// ---------------------------------------------------------------- init: category (4/thread)
__global__ void k_init4(const float* __restrict__ pred, const int* __restrict__ tgt) {
    int t = blockIdx.x * blockDim.x + threadIdx.x;
    if (t >= NN4) return;
    int i0 = t << 2;
    float4 a = *(const float4*)(pred + i0);
    float4 b = *(const float4*)(pred + NN + i0);
    int4   g = *(const int4*)(tgt + i0);
    unsigned int c0 = ((b.x > a.x) ? 1u : 0u) | ((g.x == 1) ? 2u : 0u);
    unsigned int c1 = ((b.y > a.y) ? 1u : 0u) | ((g.y == 1) ? 2u : 0u);
    unsigned int c2 = ((b.z > a.z) ? 1u : 0u) | ((g.z == 1) ? 2u : 0u);
    unsigned int c3 = ((b.w > a.w) ? 1u : 0u) | ((g.w == 1) ? 2u : 0u);
    *(unsigned int*)(d_cat + i0) = c0 | (c1 << 8) | (c2 << 16) | (c3 << 24);
}

// ---------------------------------------------------------------- hook: hint forest (4/thread)
__device__ __forceinline__ void col_hook(unsigned int B0, int jb,
                                         bool okL, bool okR, int is6mask, int* best) {
    unsigned int Bc = *(const unsigned int*)(d_cat + jb);
    unsigned int cm1 = okL ? (unsigned int)d_cat[jb - 1] : 0xFFu;
    unsigned int cp4 = okR ? (unsigned int)d_cat[jb + 4] : 0xFFu;
    unsigned int w[6] = { cm1, Bc & 0xFFu, (Bc >> 8) & 0xFFu,
                          (Bc >> 16) & 0xFFu, (Bc >> 24) & 0xFFu, cp4 };
    #pragma unroll
    for (int v = 0; v < 4; v++) {
        unsigned int c = (B0 >> (8 * v)) & 0xFFu;
        #pragma unroll
        for (int dx = -1; dx <= 1; dx++) {
            int wi = v + 1 + dx;
            if (w[wi] != c) continue;
            if (c == 0u && !((is6mask >> (dx + 1)) & 1)) continue;  // TN: 6-conn only
            int j = jb + v + dx;
            if (j < best[v]) best[v] = j;
        }
    }
}

__global__ void k_hook4() {
    int t = blockIdx.x * blockDim.x + threadIdx.x;
    if (t >= NN4) return;
    int i0 = t << 2;
    int z = i0 / SLICE; int r = i0 - z * SLICE; int y = r / WX; int x0 = r - y * WX;
    unsigned int B0 = *(const unsigned int*)(d_cat + i0);
    bool okL = (x0 > 0);
    bool okR = (x0 + 4 < WX);
    int best[4] = { i0, i0 + 1, i0 + 2, i0 + 3 };
    if (z > 0) {
        int zb = i0 - SLICE;
        if (y > 0)        col_hook(B0, zb - WX, okL, okR, 0,     best); // (-1,-1,*)
                          col_hook(B0, zb,      okL, okR, 0b010, best); // (-1, 0,*)
        if (y < HY - 1)   col_hook(B0, zb + WX, okL, okR, 0,     best); // (-1,+1,*)
    }
    if (y > 0)            col_hook(B0, i0 - WX, okL, okR, 0b010, best); // (0,-1,*)
    {
        unsigned int cm1 = okL ? (unsigned int)d_cat[i0 - 1] : 0xFFu;
        #pragma unroll
        for (int v = 0; v < 4; v++) {
            unsigned int c = (B0 >> (8 * v)) & 0xFFu;
            unsigned int cj = (v == 0) ? cm1 : ((B0 >> (8 * (v - 1))) & 0xFFu);
            int j = i0 + v - 1;
            if (cj == c && j < best[v]) best[v] = j;
        }
    }
    *(int4*)(d_parent + i0) = make_int4(best[0], best[1], best[2], best[3]);
}

// ---------------------------------------------------------------- union-find
__device__ __forceinline__ int uf_find(int x) {
    while (true) {
        int p = d_parent[x];
        if (p == x) return x;
        int gp = d_parent[p];
        if (gp == p) return p;
        d_parent[x] = gp;                // path halving
        x = gp;
    }
}

__device__ __forceinline__ void uf_union(int a, int b) {
    while (true) {
        a = uf_find(a);
        b = uf_find(b);
        if (a == b) return;
        if (a > b) { int t = a; a = b; b = t; }
        int old = atomicMin(&d_parent[b], a);
        if (old == b) return;
        b = old;
    }
}

// Scalar union with run-based pruning:
// If the left in-row neighbor shares the category (26-conn cats), this voxel
// only needs the left link plus the four dx=+1 upper-column edges; dx in {-1,0}
// upper edges are covered by earlier voxels of the same run (run start does all
// 13). TN voxels (6-conn) use their 3 face edges unconditionally.
__global__ void k_union() {
    int i = blockIdx.x * blockDim.x + threadIdx.x;
    if (i >= NN) return;
    int c = d_cat[i];
    int z = i / SLICE; int r = i - z * SLICE; int y = r / WX; int x = r - y * WX;
    if (c == 0) {                                   // TN: 6-connectivity only
        if (z > 0 && (int)d_cat[i - SLICE] == 0) uf_union(i, i - SLICE);
        if (y > 0 && (int)d_cat[i - WX]    == 0) uf_union(i, i - WX);
        if (x > 0 && (int)d_cat[i - 1]     == 0) uf_union(i, i - 1);
        return;
    }
    bool left_same = (x > 0) && ((int)d_cat[i - 1] == c);
    if (left_same) {
        uf_union(i, i - 1);
        if (x + 1 < WX) {                           // four dx=+1 upper edges
            if (z > 0) {
                int zb = i - SLICE + 1;
                if (y > 0       && (int)d_cat[zb - WX] == c) uf_union(i, zb - WX);
                if (               (int)d_cat[zb]      == c) uf_union(i, zb);
                if (y < HY - 1  && (int)d_cat[zb + WX] == c) uf_union(i, zb + WX);
            }
            if (y > 0 && (int)d_cat[i - WX + 1] == c) uf_union(i, i - WX + 1);
        }
        return;
    }
    #pragma unroll
    for (int k = 0; k < 13; k++) {                  // run start: all 13
        int nz = z + c_off[k][0], ny = y + c_off[k][1], nx = x + c_off[k][2];
        if (nz < 0 || ny < 0 || ny >= HY || nx < 0 || nx >= WX) continue;
        int j = i + c_off[k][0] * SLICE + c_off[k][1] * WX + c_off[k][2];
        if ((int)d_cat[j] == c) uf_union(i, j);
    }
}

__global__ void k_flatten4() {
    int t = blockIdx.x * blockDim.x + threadIdx.x;
    if (t >= NN4) return;
    int i0 = t << 2;
    int4 L;
    L.x = uf_find(i0);
    L.y = uf_find(i0 + 1);
    L.z = uf_find(i0 + 2);
    L.w = uf_find(i0 + 3);
    *(int4*)(d_labels + i0) = L;     // root == component min index
}

// ---------------------------------------------------------------- region graph,
// emulating the reference's int32-wraparound key semantics (JAX x64 disabled).
// Fast skip: key = Li*N + Lj (mod 2^32) can only land in [0, 2^28) if
// base = Li*N mod 2^32 is < 2^28 (no wrap) or >= 2^32-N (wrap, key < N).
// ~15/16 of voxels fail for all 26 neighbors -> skip column loads entirely.
__device__ __forceinline__ void edge_try(unsigned int key) {
    if (key >= (1u << 28)) return;                  // negative or >= SENT32: dropped
    unsigned int word = key >> 5;
    unsigned int bit = 1u << (key & 31u);
    if (d_bitmap[word] & bit) return;               // bits only ever set: safe skip
    unsigned int old = atomicOr(&d_bitmap[word], bit);
    if (old & bit) return;
    int src = (int)(key / NNU);                     // 0..334
    int dst = (int)(key - (unsigned int)src * NNU); // 0..N-1
    int c2 = (int)d_cat[dst];
    if (c2 == 3)      atomicAdd(&d_fg[src], 1);
    else if (c2 == 0) atomicAdd(&d_bg[src], 1);
}

__device__ __forceinline__ void col_edges(const unsigned int* Lv, unsigned int pmask,
                                          int jb, bool okL, bool okR, bool center) {
    int4 B = *(const int4*)(d_labels + jb);
    int wm1 = okL ? d_labels[jb - 1] : 0;
    int wp4 = okR ? d_labels[jb + 4] : 0;
    int w[6] = { wm1, B.x, B.y, B.z, B.w, wp4 };
    #pragma unroll
    for (int v = 0; v < 4; v++) {
        if (!((pmask >> v) & 1u)) continue;         // this label can't emit keys
        unsigned int L = Lv[v];
        unsigned int base = L * NNU;                // wraps mod 2^32 like the reference
        #pragma unroll
        for (int dx = -1; dx <= 1; dx++) {
            if (center && dx == 0) continue;        // self
            int wi = v + 1 + dx;
            if (wi == 0 && !okL) continue;
            if (wi == 5 && !okR) continue;
            unsigned int Lj = (unsigned int)w[wi];
            if (Lj == L) continue;
            edge_try(base + Lj);
        }
    }
}

__global__ void k_edges4() {
    int t = blockIdx.x * blockDim.x + threadIdx.x;
    if (t >= NN4) return;
    int i0 = t << 2;
    int4 Li = *(const int4*)(d_labels + i0);
    unsigned int Lv[4] = { (unsigned int)Li.x, (unsigned int)Li.y,
                           (unsigned int)Li.z, (unsigned int)Li.w };
    unsigned int pmask = 0u;
    #pragma unroll
    for (int v = 0; v < 4; v++) {
        unsigned int base = Lv[v] * NNU;
        if (base < (1u << 28) || base >= WRAP_LO) pmask |= (1u << v);
    }
    if (pmask == 0u) return;                        // ~15/16 of groups exit here
    int z = i0 / SLICE; int r = i0 - z * SLICE; int y = r / WX; int x0 = r - y * WX;
    bool okL = (x0 > 0);
    bool okR = (x0 + 4 < WX);
    #pragma unroll
    for (int dz = -1; dz <= 1; dz++) {
        int nz = z + dz;
        if (nz < 0 || nz >= DZ) continue;
        #pragma unroll
        for (int dy = -1; dy <= 1; dy++) {
            int ny = y + dy;
            if (ny < 0 || ny >= HY) continue;
            int jb = i0 + dz * SLICE + dy * WX;
            col_edges(Lv, pmask, jb, okL, okR, (dz == 0 && dy == 0));
        }
    }
}

// ---------------------------------------------------------------- per-voxel loss,
// warp-aggregated: one atomic pair per distinct label per warp per sub-voxel.
__global__ void k_loss4(const float* __restrict__ pred) {
    int t = blockIdx.x * blockDim.x + threadIdx.x;
    int i0 = t << 2;
    unsigned int cc = *(const unsigned int*)(d_cat + i0);
    int4 Li = *(const int4*)(d_labels + i0);
    int Ls[4] = { Li.x, Li.y, Li.z, Li.w };
    int lane = threadIdx.x & 31;
    #pragma unroll
    for (int v = 0; v < 4; v++) {
        unsigned int c = (cc >> (8 * v)) & 0xFFu;
        int L = Ls[v];
        bool active = (c == 1u || c == 2u);
        if (active && L < MAXSRC && d_fg[L] == 1 && d_bg[L] == 1) active = false;
        unsigned long long fx = 0ull;
        if (active) {
            int i = i0 + v;
            float p0 = pred[i], p1 = pred[NN + i];
            float p = 1.0f / (1.0f + expf(p0 - p1));    // softmax channel 1
            float g = (c == 2u) ? 1.0f : 0.0f;          // FN => gt foreground
            float d = p - g;
            double vv = (double)d * (double)d;          // in [0,1]
            fx = (unsigned long long)(vv * 4294967296.0);  // Q32.32
        }
        int key = active ? L : -1;
        unsigned int m = __match_any_sync(0xFFFFFFFFu, key);
        unsigned long long s = 0ull;
        int cs = 0;
        unsigned int mm = m;
        while (mm) {                                   // same trip count for all of m
            int b = __ffs(mm) - 1;
            s  += __shfl_sync(m, fx, b);               // mask = group -> converged
            cs += (int)__shfl_sync(m, (int)(active ? 1 : 0), b);
            mm &= mm - 1;
        }
        int leader = __ffs(m) - 1;
        if (active && lane == leader) {
            atomicAdd(&d_lsum[L], s);
            atomicAdd(&d_ccnt[L], cs);
        }
    }
}

// ---------------------------------------------------------------- per-region mean -> global
__global__ void k_regions4() {
    int t = blockIdx.x * blockDim.x + threadIdx.x;
    if (t >= NN4) return;
    int i0 = t << 2;
    int4 c4 = *(const int4*)(d_ccnt + i0);
    if ((c4.x | c4.y | c4.z | c4.w) == 0) return;
    int cs[4] = { c4.x, c4.y, c4.z, c4.w };
    #pragma unroll
    for (int v = 0; v < 4; v++) {
        int cnt = cs[v];
        if (cnt <= 0) continue;
        double mean = (double)d_lsum[i0 + v] * (1.0 / 4294967296.0) / (double)cnt;
        atomicAdd(&d_gsum, (unsigned long long)(mean * 1073741824.0));    // Q34.30
        atomicAdd(&d_gregs, 1);
    }
}

__global__ void k_final(float* __restrict__ out) {
    int r = d_gregs;
    double s = (double)d_gsum * (1.0 / 1073741824.0);
    out[0] = (r > 0) ? (float)(s / (double)r) : 0.0f;
}

// ---------------------------------------------------------------- launch
extern "C" void kernel_launch(void* const* d_in, const int* in_sizes, int n_in,
                              void* d_out, int out_size) {
    const float* pred;
    const int*   tgt;
    if (in_sizes[0] == 2 * NN) {
        pred = (const float*)d_in[0];
        tgt  = (const int*)d_in[1];
    } else {
        pred = (const float*)d_in[1];
        tgt  = (const int*)d_in[0];
    }
    const int T = 256;
    const int G4 = (NN4 + T - 1) / T;   // 784 blocks
    const int GB = (NN + T - 1) / T;    // 3136 blocks
    k_clear   <<<2048, T>>>();
    k_init4   <<<G4, T>>>(pred, tgt);
    k_hook4   <<<G4, T>>>();
    k_union   <<<GB, T>>>();            // 4th launch -> profiled slot
    k_flatten4<<<G4, T>>>();
    k_edges4  <<<G4, T>>>();
    k_loss4   <<<G4, T>>>(pred);
    k_regions4<<<G4, T>>>();
    k_final   <<<1, 1>>>((float*)d_out);
}

// round 14
// speedup vs baseline: 1.0306x; 1.0306x over previous
#include <cuda_runtime.h>
#include <math.h>

#define DZ 64
#define HY 112
#define WX 112
#define SLICE (HY*WX)        /* 12544 */
#define NN (DZ*SLICE)        /* 802816 */
#define NNU 802816u
#define NN4 (NN/4)           /* 200704 */
#define BM_WORDS (1u<<23)    /* bitmap for key values in [0, 2^28): 32MB */
#define MAXSRC 512           /* valid src labels are <= 334 */
#define WRAP_LO ((unsigned int)(0x100000000ull - NNU))  /* base >= this can wrap */

__device__ int                d_parent[NN];
__device__ int                d_labels[NN];
__device__ unsigned char      d_cat[NN];
__device__ int                d_fg[MAXSRC];
__device__ int                d_bg[MAXSRC];
__device__ unsigned long long d_lsum[NN];
__device__ int                d_ccnt[NN];
__device__ unsigned int       d_bitmap[BM_WORDS];
__device__ unsigned long long d_gsum;
__device__ int                d_gregs;

// 13 lexicographically-negative offsets {dz,dy,dx,is6}
__device__ __constant__ int c_off[13][4] = {
    {-1,-1,-1,0},{-1,-1, 0,0},{-1,-1, 1,0},
    {-1, 0,-1,0},{-1, 0, 0,1},{-1, 0, 1,0},
    {-1, 1,-1,0},{-1, 1, 0,0},{-1, 1, 1,0},
    { 0,-1,-1,0},{ 0,-1, 0,1},{ 0,-1, 1,0},
    { 0, 0,-1,1}
};

// ---------------------------------------------------------------- clear (uint4)
__global__ void k_clear() {
    unsigned int idx = blockIdx.x * blockDim.x + threadIdx.x;
    unsigned int stride = gridDim.x * blockDim.x;
    uint4 z4 = make_uint4(0u, 0u, 0u, 0u);
    uint4* bm = (uint4*)d_bitmap;                   // 2M uint4
    for (unsigned int i = idx; i < (BM_WORDS >> 2); i += stride) bm[i] = z4;
    uint4* ls = (uint4*)d_lsum;                     // NN/2 uint4
    for (unsigned int i = idx; i < (NN >> 1); i += stride) ls[i] = z4;
    uint4* cc = (uint4*)d_ccnt;                     // NN/4 uint4
    for (unsigned int i = idx; i < (NN >> 2); i += stride) cc[i] = z4;
    if (idx < MAXSRC) { d_fg[idx] = 0; d_bg[idx] = 0; }
    if (idx == 0) { d_gsum = 0ull; d_gregs = 0; }
}

// ---------------------------------------------------------------- init: category (4/thread)
__global__ void k_init4(const float* __restrict__ pred, const int* __restrict__ tgt) {
    int t = blockIdx.x * blockDim.x + threadIdx.x;
    if (t >= NN4) return;
    int i0 = t << 2;
    float4 a = *(const float4*)(pred + i0);
    float4 b = *(const float4*)(pred + NN + i0);
    int4   g = *(const int4*)(tgt + i0);
    unsigned int c0 = ((b.x > a.x) ? 1u : 0u) | ((g.x == 1) ? 2u : 0u);
    unsigned int c1 = ((b.y > a.y) ? 1u : 0u) | ((g.y == 1) ? 2u : 0u);
    unsigned int c2 = ((b.z > a.z) ? 1u : 0u) | ((g.z == 1) ? 2u : 0u);
    unsigned int c3 = ((b.w > a.w) ? 1u : 0u) | ((g.w == 1) ? 2u : 0u);
    *(unsigned int*)(d_cat + i0) = c0 | (c1 << 8) | (c2 << 16) | (c3 << 24);
}

// ---------------------------------------------------------------- hook: hint forest (4/thread)
__device__ __forceinline__ void col_hook(unsigned int B0, int jb,
                                         bool okL, bool okR, int is6mask, int* best) {
    unsigned int Bc = *(const unsigned int*)(d_cat + jb);
    unsigned int cm1 = okL ? (unsigned int)d_cat[jb - 1] : 0xFFu;
    unsigned int cp4 = okR ? (unsigned int)d_cat[jb + 4] : 0xFFu;
    unsigned int w[6] = { cm1, Bc & 0xFFu, (Bc >> 8) & 0xFFu,
                          (Bc >> 16) & 0xFFu, (Bc >> 24) & 0xFFu, cp4 };
    #pragma unroll
    for (int v = 0; v < 4; v++) {
        unsigned int c = (B0 >> (8 * v)) & 0xFFu;
        #pragma unroll
        for (int dx = -1; dx <= 1; dx++) {
            int wi = v + 1 + dx;
            if (w[wi] != c) continue;
            if (c == 0u && !((is6mask >> (dx + 1)) & 1)) continue;  // TN: 6-conn only
            int j = jb + v + dx;
            if (j < best[v]) best[v] = j;
        }
    }
}

__global__ void k_hook4() {
    int t = blockIdx.x * blockDim.x + threadIdx.x;
    if (t >= NN4) return;
    int i0 = t << 2;
    int z = i0 / SLICE; int r = i0 - z * SLICE; int y = r / WX; int x0 = r - y * WX;
    unsigned int B0 = *(const unsigned int*)(d_cat + i0);
    bool okL = (x0 > 0);
    bool okR = (x0 + 4 < WX);
    int best[4] = { i0, i0 + 1, i0 + 2, i0 + 3 };
    if (z > 0) {
        int zb = i0 - SLICE;
        if (y > 0)        col_hook(B0, zb - WX, okL, okR, 0,     best); // (-1,-1,*)
                          col_hook(B0, zb,      okL, okR, 0b010, best); // (-1, 0,*)
        if (y < HY - 1)   col_hook(B0, zb + WX, okL, okR, 0,     best); // (-1,+1,*)
    }
    if (y > 0)            col_hook(B0, i0 - WX, okL, okR, 0b010, best); // (0,-1,*)
    {
        unsigned int cm1 = okL ? (unsigned int)d_cat[i0 - 1] : 0xFFu;
        #pragma unroll
        for (int v = 0; v < 4; v++) {
            unsigned int c = (B0 >> (8 * v)) & 0xFFu;
            unsigned int cj = (v == 0) ? cm1 : ((B0 >> (8 * (v - 1))) & 0xFFu);
            int j = i0 + v - 1;
            if (cj == c && j < best[v]) best[v] = j;
        }
    }
    *(int4*)(d_parent + i0) = make_int4(best[0], best[1], best[2], best[3]);
}

// ---------------------------------------------------------------- union-find
__device__ __forceinline__ int uf_find(int x) {
    while (true) {
        int p = d_parent[x];
        if (p == x) return x;
        int gp = d_parent[p];
        if (gp == p) return p;
        d_parent[x] = gp;                // path halving
        x = gp;
    }
}

__device__ __forceinline__ void uf_union(int a, int b) {
    while (true) {
        a = uf_find(a);
        b = uf_find(b);
        if (a == b) return;
        if (a > b) { int t = a; a = b; b = t; }
        int old = atomicMin(&d_parent[b], a);
        if (old == b) return;
        b = old;
    }
}

// Scalar union, uniform control flow: 1 voxel/thread over all 13 negative
// offsets. (Run-based pruning was tried and regressed: divergence cost more
// than the redundant unions, which exit cheaply at a==b thanks to the hook.)
__global__ void k_union() {
    int i = blockIdx.x * blockDim.x + threadIdx.x;
    if (i >= NN) return;
    int c = __ldg(&d_cat[i]);
    int z = i / SLICE; int r = i - z * SLICE; int y = r / WX; int x = r - y * WX;
    #pragma unroll
    for (int k = 0; k < 13; k++) {
        if (c == 0 && !c_off[k][3]) continue;      // TN: 6-connectivity only
        int nz = z + c_off[k][0], ny = y + c_off[k][1], nx = x + c_off[k][2];
        if (nz < 0 || ny < 0 || ny >= HY || nx < 0 || nx >= WX) continue;
        int j = i + c_off[k][0] * SLICE + c_off[k][1] * WX + c_off[k][2];
        if ((int)__ldg(&d_cat[j]) == c) uf_union(i, j);
    }
}

__global__ void k_flatten4() {
    int t = blockIdx.x * blockDim.x + threadIdx.x;
    if (t >= NN4) return;
    int i0 = t << 2;
    int4 L;
    L.x = uf_find(i0);
    L.y = uf_find(i0 + 1);
    L.z = uf_find(i0 + 2);
    L.w = uf_find(i0 + 3);
    *(int4*)(d_labels + i0) = L;     // root == component min index
}

// ---------------------------------------------------------------- region graph,
// emulating the reference's int32-wraparound key semantics (JAX x64 disabled).
// Fast skip: key = Li*N + Lj (mod 2^32) lands in [0, 2^28) only if
// base = Li*N mod 2^32 is < 2^28 (no wrap) or >= 2^32-N (wrap, key < N).
__device__ __forceinline__ void edge_try(unsigned int key) {
    if (key >= (1u << 28)) return;                  // negative or >= SENT32: dropped
    unsigned int word = key >> 5;
    unsigned int bit = 1u << (key & 31u);
    if (d_bitmap[word] & bit) return;               // bits only ever set: safe skip
    unsigned int old = atomicOr(&d_bitmap[word], bit);
    if (old & bit) return;
    int src = (int)(key / NNU);                     // 0..334
    int dst = (int)(key - (unsigned int)src * NNU); // 0..N-1
    int c2 = (int)d_cat[dst];
    if (c2 == 3)      atomicAdd(&d_fg[src], 1);
    else if (c2 == 0) atomicAdd(&d_bg[src], 1);
}

__device__ __forceinline__ void col_edges(const unsigned int* Lv, unsigned int pmask,
                                          int jb, bool okL, bool okR, bool center) {
    int4 B = *(const int4*)(d_labels + jb);
    int wm1 = okL ? d_labels[jb - 1] : 0;
    int wp4 = okR ? d_labels[jb + 4] : 0;
    int w[6] = { wm1, B.x, B.y, B.z, B.w, wp4 };
    #pragma unroll
    for (int v = 0; v < 4; v++) {
        if (!((pmask >> v) & 1u)) continue;         // this label can't emit keys
        unsigned int L = Lv[v];
        unsigned int base = L * NNU;                // wraps mod 2^32 like the reference
        #pragma unroll
        for (int dx = -1; dx <= 1; dx++) {
            if (center && dx == 0) continue;        // self
            int wi = v + 1 + dx;
            if (wi == 0 && !okL) continue;
            if (wi == 5 && !okR) continue;
            unsigned int Lj = (unsigned int)w[wi];
            if (Lj == L) continue;
            edge_try(base + Lj);
        }
    }
}

__global__ void k_edges4() {
    int t = blockIdx.x * blockDim.x + threadIdx.x;
    if (t >= NN4) return;
    int i0 = t << 2;
    int4 Li = *(const int4*)(d_labels + i0);
    unsigned int Lv[4] = { (unsigned int)Li.x, (unsigned int)Li.y,
                           (unsigned int)Li.z, (unsigned int)Li.w };
    unsigned int pmask = 0u;
    #pragma unroll
    for (int v = 0; v < 4; v++) {
        unsigned int base = Lv[v] * NNU;
        if (base < (1u << 28) || base >= WRAP_LO) pmask |= (1u << v);
    }
    if (pmask == 0u) return;                        // ~15/16 of groups exit here
    int z = i0 / SLICE; int r = i0 - z * SLICE; int y = r / WX; int x0 = r - y * WX;
    bool okL = (x0 > 0);
    bool okR = (x0 + 4 < WX);
    #pragma unroll
    for (int dz = -1; dz <= 1; dz++) {
        int nz = z + dz;
        if (nz < 0 || nz >= DZ) continue;
        #pragma unroll
        for (int dy = -1; dy <= 1; dy++) {
            int ny = y + dy;
            if (ny < 0 || ny >= HY) continue;
            int jb = i0 + dz * SLICE + dy * WX;
            col_edges(Lv, pmask, jb, okL, okR, (dz == 0 && dy == 0));
        }
    }
}

// ---------------------------------------------------------------- per-voxel loss,
// warp-aggregated: one atomic pair per distinct label per warp per sub-voxel.
__global__ void k_loss4(const float* __restrict__ pred) {
    int t = blockIdx.x * blockDim.x + threadIdx.x;
    int i0 = t << 2;
    unsigned int cc = *(const unsigned int*)(d_cat + i0);
    int4 Li = *(const int4*)(d_labels + i0);
    int Ls[4] = { Li.x, Li.y, Li.z, Li.w };
    int lane = threadIdx.x & 31;
    #pragma unroll
    for (int v = 0; v < 4; v++) {
        unsigned int c = (cc >> (8 * v)) & 0xFFu;
        int L = Ls[v];
        bool active = (c == 1u || c == 2u);
        if (active && L < MAXSRC && d_fg[L] == 1 && d_bg[L] == 1) active = false;
        unsigned long long fx = 0ull;
        if (active) {
            int i = i0 + v;
            float p0 = pred[i], p1 = pred[NN + i];
            float p = 1.0f / (1.0f + expf(p0 - p1));    // softmax channel 1
            float g = (c == 2u) ? 1.0f : 0.0f;          // FN => gt foreground
            float d = p - g;
            double vv = (double)d * (double)d;          // in [0,1]
            fx = (unsigned long long)(vv * 4294967296.0);  // Q32.32
        }
        int key = active ? L : -1;
        unsigned int m = __match_any_sync(0xFFFFFFFFu, key);
        unsigned long long s = 0ull;
        int cs = 0;
        unsigned int mm = m;
        while (mm) {                                   // same trip count for all of m
            int b = __ffs(mm) - 1;
            s  += __shfl_sync(m, fx, b);               // mask = group -> converged
            cs += (int)__shfl_sync(m, (int)(active ? 1 : 0), b);
            mm &= mm - 1;
        }
        int leader = __ffs(m) - 1;
        if (active && lane == leader) {
            atomicAdd(&d_lsum[L], s);
            atomicAdd(&d_ccnt[L], cs);
        }
    }
}

// ---------------------------------------------------------------- per-region mean -> global
__global__ void k_regions4() {
    int t = blockIdx.x * blockDim.x + threadIdx.x;
    if (t >= NN4) return;
    int i0 = t << 2;
    int4 c4 = *(const int4*)(d_ccnt + i0);
    if ((c4.x | c4.y | c4.z | c4.w) == 0) return;
    int cs[4] = { c4.x, c4.y, c4.z, c4.w };
    #pragma unroll
    for (int v = 0; v < 4; v++) {
        int cnt = cs[v];
        if (cnt <= 0) continue;
        double mean = (double)d_lsum[i0 + v] * (1.0 / 4294967296.0) / (double)cnt;
        atomicAdd(&d_gsum, (unsigned long long)(mean * 1073741824.0));    // Q34.30
        atomicAdd(&d_gregs, 1);
    }
}

__global__ void k_final(float* __restrict__ out) {
    int r = d_gregs;
    double s = (double)d_gsum * (1.0 / 1073741824.0);
    out[0] = (r > 0) ? (float)(s / (double)r) : 0.0f;
}

// ---------------------------------------------------------------- launch
extern "C" void kernel_launch(void* const* d_in, const int* in_sizes, int n_in,
                              void* d_out, int out_size) {
    const float* pred;
    const int*   tgt;
    if (in_sizes[0] == 2 * NN) {
        pred = (const float*)d_in[0];
        tgt  = (const int*)d_in[1];
    } else {
        pred = (const float*)d_in[1];
        tgt  = (const int*)d_in[0];
    }
    const int T = 256;
    const int G4 = (NN4 + T - 1) / T;   // 784 blocks
    const int GB = (NN + T - 1) / T;    // 3136 blocks
    k_clear   <<<2048, T>>>();
    k_init4   <<<G4, T>>>(pred, tgt);
    k_hook4   <<<G4, T>>>();
    k_union   <<<GB, T>>>();            // 4th launch -> profiled slot
    k_flatten4<<<G4, T>>>();
    k_edges4  <<<G4, T>>>();
    k_loss4   <<<G4, T>>>(pred);
    k_regions4<<<G4, T>>>();
    k_final   <<<1, 1>>>((float*)d_out);
}

// round 17
// speedup vs baseline: 1.0431x; 1.0122x over previous
#include <cuda_runtime.h>
#include <math.h>

#define DZ 64
#define HY 112
#define WX 112
#define SLICE (HY*WX)        /* 12544 */
#define NN (DZ*SLICE)        /* 802816 */
#define NNU 802816u
#define NN4 (NN/4)           /* 200704 */
#define BM_WORDS (1u<<23)    /* bitmap for key values in [0, 2^28): 32MB */
#define MAXSRC 512           /* valid src labels are <= 334 */
#define WRAP_LO ((unsigned int)(0x100000000ull - NNU))  /* base >= this can wrap */

__device__ int                d_parent[NN];
__device__ int                d_labels[NN];
__device__ unsigned char      d_cat[NN];
__device__ int                d_fg[MAXSRC];
__device__ int                d_bg[MAXSRC];
__device__ unsigned long long d_lsum[NN];
__device__ int                d_ccnt[NN];
__device__ unsigned int       d_bitmap[BM_WORDS];
__device__ unsigned long long d_gsum;
__device__ int                d_gregs;
__device__ unsigned int      d_ticket;

// 13 lexicographically-negative offsets {dz,dy,dx,is6}
__device__ __constant__ int c_off[13][4] = {
    {-1,-1,-1,0},{-1,-1, 0,0},{-1,-1, 1,0},
    {-1, 0,-1,0},{-1, 0, 0,1},{-1, 0, 1,0},
    {-1, 1,-1,0},{-1, 1, 0,0},{-1, 1, 1,0},
    { 0,-1,-1,0},{ 0,-1, 0,1},{ 0,-1, 1,0},
    { 0, 0,-1,1}
};

// ---------------------------------------------------------------- init: category (4/thread)
// + fused clears (bitmap / lsum / ccnt / fg / bg / globals): consumers run >= 2
// kernels later, so ordering within this kernel is irrelevant.
__global__ void k_init4(const float* __restrict__ pred, const int* __restrict__ tgt) {
    unsigned int t = blockIdx.x * blockDim.x + threadIdx.x;
    unsigned int stride = gridDim.x * blockDim.x;
    if (t < NN4) {
        int i0 = (int)(t << 2);
        float4 a = *(const float4*)(pred + i0);
        float4 b = *(const float4*)(pred + NN + i0);
        int4   g = *(const int4*)(tgt + i0);
        unsigned int c0 = ((b.x > a.x) ? 1u : 0u) | ((g.x == 1) ? 2u : 0u);
        unsigned int c1 = ((b.y > a.y) ? 1u : 0u) | ((g.y == 1) ? 2u : 0u);
        unsigned int c2 = ((b.z > a.z) ? 1u : 0u) | ((g.z == 1) ? 2u : 0u);
        unsigned int c3 = ((b.w > a.w) ? 1u : 0u) | ((g.w == 1) ? 2u : 0u);
        *(unsigned int*)(d_cat + i0) = c0 | (c1 << 8) | (c2 << 16) | (c3 << 24);
    }
    uint4 z4 = make_uint4(0u, 0u, 0u, 0u);
    uint4* bm = (uint4*)d_bitmap;                   // 2M uint4
    for (unsigned int i = t; i < (BM_WORDS >> 2); i += stride) bm[i] = z4;
    uint4* ls = (uint4*)d_lsum;                     // NN/2 uint4
    for (unsigned int i = t; i < (NN >> 1); i += stride) ls[i] = z4;
    uint4* cc = (uint4*)d_ccnt;                     // NN/4 uint4
    for (unsigned int i = t; i < (NN >> 2); i += stride) cc[i] = z4;
    if (t < MAXSRC) { d_fg[t] = 0; d_bg[t] = 0; }
    if (t == 0) { d_gsum = 0ull; d_gregs = 0; d_ticket = 0u; }
}

// ---------------------------------------------------------------- hook: hint forest (4/thread)
__device__ __forceinline__ void col_hook(unsigned int B0, int jb,
                                         bool okL, bool okR, int is6mask, int* best) {
    unsigned int Bc = *(const unsigned int*)(d_cat + jb);
    unsigned int cm1 = okL ? (unsigned int)d_cat[jb - 1] : 0xFFu;
    unsigned int cp4 = okR ? (unsigned int)d_cat[jb + 4] : 0xFFu;
    unsigned int w[6] = { cm1, Bc & 0xFFu, (Bc >> 8) & 0xFFu,
                          (Bc >> 16) & 0xFFu, (Bc >> 24) & 0xFFu, cp4 };
    #pragma unroll
    for (int v = 0; v < 4; v++) {
        unsigned int c = (B0 >> (8 * v)) & 0xFFu;
        #pragma unroll
        for (int dx = -1; dx <= 1; dx++) {
            int wi = v + 1 + dx;
            if (w[wi] != c) continue;
            if (c == 0u && !((is6mask >> (dx + 1)) & 1)) continue;  // TN: 6-conn only
            int j = jb + v + dx;
            if (j < best[v]) best[v] = j;
        }
    }
}

__global__ void k_hook4() {
    int t = blockIdx.x * blockDim.x + threadIdx.x;
    if (t >= NN4) return;
    int i0 = t << 2;
    int z = i0 / SLICE; int r = i0 - z * SLICE; int y = r / WX; int x0 = r - y * WX;
    unsigned int B0 = *(const unsigned int*)(d_cat + i0);
    bool okL = (x0 > 0);
    bool okR = (x0 + 4 < WX);
    int best[4] = { i0, i0 + 1, i0 + 2, i0 + 3 };
    if (z > 0) {
        int zb = i0 - SLICE;
        if (y > 0)        col_hook(B0, zb - WX, okL, okR, 0,     best); // (-1,-1,*)
                          col_hook(B0, zb,      okL, okR, 0b010, best); // (-1, 0,*)
        if (y < HY - 1)   col_hook(B0, zb + WX, okL, okR, 0,     best); // (-1,+1,*)
    }
    if (y > 0)            col_hook(B0, i0 - WX, okL, okR, 0b010, best); // (0,-1,*)
    {
        unsigned int cm1 = okL ? (unsigned int)d_cat[i0 - 1] : 0xFFu;
        #pragma unroll
        for (int v = 0; v < 4; v++) {
            unsigned int c = (B0 >> (8 * v)) & 0xFFu;
            unsigned int cj = (v == 0) ? cm1 : ((B0 >> (8 * (v - 1))) & 0xFFu);
            int j = i0 + v - 1;
            if (cj == c && j < best[v]) best[v] = j;
        }
    }
    *(int4*)(d_parent + i0) = make_int4(best[0], best[1], best[2], best[3]);
}

// ---------------------------------------------------------------- union-find
__device__ __forceinline__ int uf_find(int x) {
    while (true) {
        int p = d_parent[x];
        if (p == x) return x;
        int gp = d_parent[p];
        if (gp == p) return p;
        d_parent[x] = gp;                // path halving
        x = gp;
    }
}

// Union returning the (current) root of the merged component. Re-finds a on
// entry, so callers may pass a stale root.
__device__ __forceinline__ int uf_union_ret(int a, int b) {
    while (true) {
        a = uf_find(a);
        b = uf_find(b);
        if (a == b) return a;
        if (a > b) { int t = a; a = b; b = t; }
        int old = atomicMin(&d_parent[b], a);
        if (old == b) return a;
        b = old;
    }
}

// Scalar union, uniform control flow, cached running root:
// each edge reuses the running root ri instead of re-finding i from scratch.
// The hook edge (j == current parent[i]) is skipped -- parent[i] is always an
// ancestor, i.e. already in i's component.
__global__ void k_union() {
    int i = blockIdx.x * blockDim.x + threadIdx.x;
    if (i >= NN) return;
    int c = __ldg(&d_cat[i]);
    int hint = d_parent[i];
    int z = i / SLICE; int r = i - z * SLICE; int y = r / WX; int x = r - y * WX;
    int ri = i;
    #pragma unroll
    for (int k = 0; k < 13; k++) {
        if (c == 0 && !c_off[k][3]) continue;      // TN: 6-connectivity only
        int nz = z + c_off[k][0], ny = y + c_off[k][1], nx = x + c_off[k][2];
        if (nz < 0 || ny < 0 || ny >= HY || nx < 0 || nx >= WX) continue;
        int j = i + c_off[k][0] * SLICE + c_off[k][1] * WX + c_off[k][2];
        if (j == hint) continue;                   // already an ancestor
        if ((int)__ldg(&d_cat[j]) == c) ri = uf_union_ret(ri, j);
    }
}

__global__ void k_flatten4() {
    int t = blockIdx.x * blockDim.x + threadIdx.x;
    if (t >= NN4) return;
    int i0 = t << 2;
    int4 L;
    L.x = uf_find(i0);
    L.y = uf_find(i0 + 1);
    L.z = uf_find(i0 + 2);
    L.w = uf_find(i0 + 3);
    *(int4*)(d_labels + i0) = L;     // root == component min index
}

// ---------------------------------------------------------------- region graph,
// emulating the reference's int32-wraparound key semantics (JAX x64 disabled).
__device__ __forceinline__ void edge_try(unsigned int key) {
    if (key >= (1u << 28)) return;                  // negative or >= SENT32: dropped
    unsigned int word = key >> 5;
    unsigned int bit = 1u << (key & 31u);
    if (d_bitmap[word] & bit) return;               // bits only ever set: safe skip
    unsigned int old = atomicOr(&d_bitmap[word], bit);
    if (old & bit) return;
    int src = (int)(key / NNU);                     // 0..334
    int dst = (int)(key - (unsigned int)src * NNU); // 0..N-1
    int c2 = (int)d_cat[dst];
    if (c2 == 3)      atomicAdd(&d_fg[src], 1);
    else if (c2 == 0) atomicAdd(&d_bg[src], 1);
}

__device__ __forceinline__ void col_edges(const unsigned int* Lv, unsigned int pmask,
                                          int jb, bool okL, bool okR, bool center) {
    int4 B = *(const int4*)(d_labels + jb);
    int wm1 = okL ? d_labels[jb - 1] : 0;
    int wp4 = okR ? d_labels[jb + 4] : 0;
    int w[6] = { wm1, B.x, B.y, B.z, B.w, wp4 };
    #pragma unroll
    for (int v = 0; v < 4; v++) {
        if (!((pmask >> v) & 1u)) continue;         // this label can't emit keys
        unsigned int L = Lv[v];
        unsigned int base = L * NNU;                // wraps mod 2^32 like the reference
        #pragma unroll
        for (int dx = -1; dx <= 1; dx++) {
            if (center && dx == 0) continue;        // self
            int wi = v + 1 + dx;
            if (wi == 0 && !okL) continue;
            if (wi == 5 && !okR) continue;
            unsigned int Lj = (unsigned int)w[wi];
            if (Lj == L) continue;
            edge_try(base + Lj);
        }
    }
}

__global__ void k_edges4() {
    int t = blockIdx.x * blockDim.x + threadIdx.x;
    if (t >= NN4) return;
    int i0 = t << 2;
    int4 Li = *(const int4*)(d_labels + i0);
    unsigned int Lv[4] = { (unsigned int)Li.x, (unsigned int)Li.y,
                           (unsigned int)Li.z, (unsigned int)Li.w };
    unsigned int pmask = 0u;
    #pragma unroll
    for (int v = 0; v < 4; v++) {
        unsigned int base = Lv[v] * NNU;
        if (base < (1u << 28) || base >= WRAP_LO) pmask |= (1u << v);
    }
    if (pmask == 0u) return;
    int z = i0 / SLICE; int r = i0 - z * SLICE; int y = r / WX; int x0 = r - y * WX;
    bool okL = (x0 > 0);
    bool okR = (x0 + 4 < WX);
    #pragma unroll
    for (int dz = -1; dz <= 1; dz++) {
        int nz = z + dz;
        if (nz < 0 || nz >= DZ) continue;
        #pragma unroll
        for (int dy = -1; dy <= 1; dy++) {
            int ny = y + dy;
            if (ny < 0 || ny >= HY) continue;
            int jb = i0 + dz * SLICE + dy * WX;
            col_edges(Lv, pmask, jb, okL, okR, (dz == 0 && dy == 0));
        }
    }
}

// ---------------------------------------------------------------- per-voxel loss,
// warp-aggregated: one atomic pair per distinct label per warp per sub-voxel.
__global__ void k_loss4(const float* __restrict__ pred) {
    int t = blockIdx.x * blockDim.x + threadIdx.x;
    int i0 = t << 2;
    unsigned int cc = *(const unsigned int*)(d_cat + i0);
    int4 Li = *(const int4*)(d_labels + i0);
    int Ls[4] = { Li.x, Li.y, Li.z, Li.w };
    int lane = threadIdx.x & 31;
    #pragma unroll
    for (int v = 0; v < 4; v++) {
        unsigned int c = (cc >> (8 * v)) & 0xFFu;
        int L = Ls[v];
        bool active = (c == 1u || c == 2u);
        if (active && L < MAXSRC && d_fg[L] == 1 && d_bg[L] == 1) active = false;
        unsigned long long fx = 0ull;
        if (active) {
            int i = i0 + v;
            float p0 = pred[i], p1 = pred[NN + i];
            float p = 1.0f / (1.0f + expf(p0 - p1));    // softmax channel 1
            float g = (c == 2u) ? 1.0f : 0.0f;          // FN => gt foreground
            float d = p - g;
            double vv = (double)d * (double)d;          // in [0,1]
            fx = (unsigned long long)(vv * 4294967296.0);  // Q32.32
        }
        int key = active ? L : -1;
        unsigned int m = __match_any_sync(0xFFFFFFFFu, key);
        unsigned long long s = 0ull;
        int cs = 0;
        unsigned int mm = m;
        while (mm) {                                   // same trip count for all of m
            int b = __ffs(mm) - 1;
            s  += __shfl_sync(m, fx, b);               // mask = group -> converged
            cs += (int)__shfl_sync(m, (int)(active ? 1 : 0), b);
            mm &= mm - 1;
        }
        int leader = __ffs(m) - 1;
        if (active && lane == leader) {
            atomicAdd(&d_lsum[L], s);
            atomicAdd(&d_ccnt[L], cs);
        }
    }
}

// ---------------------------------------------------------------- per-region mean
// -> global sum; last block computes the final output (ticket pattern).
__global__ void k_regions4(float* __restrict__ out, int nblocks) {
    int t = blockIdx.x * blockDim.x + threadIdx.x;
    if (t < NN4) {
        int i0 = t << 2;
        int4 c4 = *(const int4*)(d_ccnt + i0);
        if ((c4.x | c4.y | c4.z | c4.w) != 0) {
            int cs[4] = { c4.x, c4.y, c4.z, c4.w };
            #pragma unroll
            for (int v = 0; v < 4; v++) {
                int cnt = cs[v];
                if (cnt <= 0) continue;
                double mean = (double)d_lsum[i0 + v] * (1.0 / 4294967296.0) / (double)cnt;
                atomicAdd(&d_gsum, (unsigned long long)(mean * 1073741824.0)); // Q34.30
                atomicAdd(&d_gregs, 1);
            }
        }
    }
    __syncthreads();
    __threadfence();
    __shared__ unsigned int s_rank;
    if (threadIdx.x == 0) s_rank = atomicInc(&d_ticket, 0xFFFFFFFFu);
    __syncthreads();
    if (s_rank == (unsigned int)(nblocks - 1) && threadIdx.x == 0) {
        int rg = d_gregs;
        double s = (double)d_gsum * (1.0 / 1073741824.0);
        out[0] = (rg > 0) ? (float)(s / (double)rg) : 0.0f;
    }
}

// ---------------------------------------------------------------- launch
extern "C" void kernel_launch(void* const* d_in, const int* in_sizes, int n_in,
                              void* d_out, int out_size) {
    const float* pred;
    const int*   tgt;
    if (in_sizes[0] == 2 * NN) {
        pred = (const float*)d_in[0];
        tgt  = (const int*)d_in[1];
    } else {
        pred = (const float*)d_in[1];
        tgt  = (const int*)d_in[0];
    }
    const int T = 256;
    const int G4 = (NN4 + T - 1) / T;   // 784 blocks
    const int GB = (NN + T - 1) / T;    // 3136 blocks
    k_init4   <<<G4, T>>>(pred, tgt);   // + fused clears
    k_hook4   <<<G4, T>>>();
    k_union   <<<GB, T>>>();
    k_flatten4<<<G4, T>>>();            // 4th launch -> profiled slot
    k_edges4  <<<G4, T>>>();
    k_loss4   <<<G4, T>>>(pred);
    k_regions4<<<G4, T>>>((float*)d_out, G4);
    // no separate k_final: last region block writes the output
}